// round 14
// baseline (speedup 1.0000x reference)
#include <cuda_runtime.h>

// Problem constants: C=16, B=64, G=2048, S=8, L=4, infer_step=3.
#define NC 16
#define NB 64
#define NG 2048
#define NS 8
#define NL 4
#define NSTEPS 3
#define GAMMA 0.001f
#define KINV  1442.6950408889634f   /* 1000 * log2(e) */
#define GLN2  6.931471805599453e-4f /* gamma * ln(2)  */
#define BG (NB*NG)            // 131072
#define TOT (NC*NB*NG)        // 2097152
#define NBG (NB/8)            // 8 b-groups
#define NPK (NC*NBG*NG)       // 262144 packed uint4 per tensor

// u16 quantization: q = round(v * QF), v in [0,~1.003] -> q in [0, ~61620].
#define QF    61440.0f
#define INVQ  (1.0f/61440.0f)
#define MAGF  12582912.0f           /* 1.5*2^23 */
#define MAGI  0x4B400000u
#define KMF   196976.0f             /* round(KINV * 2^23 / QF), base slope */
#define EB_LIT 1065056216           /* (127<<23) - 297000 (minimax bias) */
#define EB_ONE 1065353216           /* (127<<23) */

// Scratch (no cudaMalloc allowed). Packed-u16 interchange tensors hold RAW
// quanta (renorm scales are folded into the runtime exp slope KMr and decode
// constants — a uniform input scale is just a different exp2 slope).
__device__ uint4 d_xq[NBG * NG];     // 512 KB: x pre-packed (step-0 fill source)
__device__ uint4 d_rq[NPK];          // 4 MB: raw clause softor, quantized
__device__ uint4 d_uq[2][NPK];       // 2x 4 MB: combined valuations, quantized
__device__ int4  d_itr[NC * (NG/32) * NS * 32];   // transposed indices, 4MB
__device__ unsigned d_mC[NSTEPS * NC];
__device__ unsigned d_mG[NSTEPS];

__device__ __forceinline__ float ex2f(float x) { float y; asm("ex2.approx.f32 %0, %1;" : "=f"(y) : "f"(x)); return y; }
__device__ __forceinline__ float lg2f(float x) { float y; asm("lg2.approx.f32 %0, %1;" : "=f"(y) : "f"(x)); return y; }
__device__ __forceinline__ float rcpf(float x) { float y; asm("rcp.approx.f32 %0, %1;" : "=f"(y) : "f"(x)); return y; }
__device__ __forceinline__ unsigned minu2(unsigned a, unsigned b) {
    unsigned d; asm("min.u16x2 %0, %1, %2;" : "=r"(d) : "r"(a), "r"(b)); return d;
}
__device__ __forceinline__ unsigned maxu2(unsigned a, unsigned b) {
    unsigned d; asm("max.u16x2 %0, %1, %2;" : "=r"(d) : "r"(a), "r"(b)); return d;
}
__device__ __forceinline__ unsigned prmt(unsigned a, unsigned b, unsigned c) {
    unsigned d; asm("prmt.b32 %0, %1, %2, %3;" : "=r"(d) : "r"(a), "r"(b), "r"(c)); return d;
}
__device__ __forceinline__ float dec_lo(unsigned q) {
    return __uint_as_float(prmt(q, MAGI, 0x7610u));
}
__device__ __forceinline__ float dec_hi(unsigned q) {
    return __uint_as_float(prmt(q, MAGI, 0x7632u));
}

// Order-preserving float<->uint encoding for atomicMax.
__device__ __forceinline__ unsigned fenc(float f) {
    unsigned u = __float_as_uint(f);
    return (u & 0x80000000u) ? ~u : (u | 0x80000000u);
}
__device__ __forceinline__ float fdec(unsigned u) {
    return __uint_as_float((u & 0x80000000u) ? (u ^ 0x80000000u) : ~u);
}

// One-time prologue: transpose I, init maxes, pre-pack x into d_xq.
__global__ __launch_bounds__(256) void transpose_I_kernel(const int* __restrict__ I,
                                                          const float* __restrict__ x) {
    const int t  = blockIdx.x * 256 + threadIdx.x;
    if (blockIdx.x == 0 && threadIdx.x < 64) {
        if (threadIdx.x < NSTEPS * NC) d_mC[threadIdx.x] = 0u;
        if (threadIdx.x < NSTEPS)      d_mG[threadIdx.x] = 0u;
    }
    if (blockIdx.x < 64) {                      // 16384 threads pack x (B,G) -> u16x8
        const int bg2 = t >> 11;
        const int g2  = t & 2047;
        const float* __restrict__ xp = x + (size_t)(bg2 * 8) * NG + g2;
        uint4 z;
        #pragma unroll
        for (int j = 0; j < 4; j++) {
            unsigned a = __float_as_uint(fmaf(xp[(2 * j) * NG],     QF, MAGF));
            unsigned b = __float_as_uint(fmaf(xp[(2 * j + 1) * NG], QF, MAGF));
            (&z.x)[j] = prmt(a, b, 0x5410u);
        }
        d_xq[t] = z;
    }
    const int gl = t & 31;
    const int s  = (t >> 5) & 7;
    const int gb = (t >> 8) & 63;
    const int c  = t >> 14;
    const int4* __restrict__ in = reinterpret_cast<const int4*>(I);
    d_itr[t] = in[((size_t)(c * NG + gb * 32 + gl)) * NS + s];
}

// Packed-pair softand + streaming-softor for rows (2j, 2j+1). Runtime slope
// KMr (renorm folded in) and clamp CLP2r. Diffs are half-wise non-negative,
// so 32-bit sub is an exact u16x2 SIMD sub. Only rcp touches MUFU.
#define PAIR_UPD(La, Lb, Lc, Ld, MrX, Slo, Shi)                                    \
    {                                                                              \
        unsigned pm = minu2(minu2(La, Lb), minu2(Lc, Ld));                         \
        unsigned Mn = maxu2(MrX, pm);                                              \
        unsigned q0 = minu2((La) - pm, CLP2r);                                     \
        unsigned q1 = minu2((Lb) - pm, CLP2r);                                     \
        unsigned q2 = minu2((Lc) - pm, CLP2r);                                     \
        unsigned q3 = minu2((Ld) - pm, CLP2r);                                     \
        float e0l = __int_as_float(EB_LIT - (int)(q0 & 0xFFFFu) * KMr);            \
        float e1l = __int_as_float(EB_LIT - (int)(q1 & 0xFFFFu) * KMr);            \
        float e2l = __int_as_float(EB_LIT - (int)(q2 & 0xFFFFu) * KMr);            \
        float e3l = __int_as_float(EB_LIT - (int)(q3 & 0xFFFFu) * KMr);            \
        float e0h = __int_as_float(EB_LIT - (int)(q0 >> 16) * KMr);                \
        float e1h = __int_as_float(EB_LIT - (int)(q1 >> 16) * KMr);                \
        float e2h = __int_as_float(EB_LIT - (int)(q2 >> 16) * KMr);                \
        float e3h = __int_as_float(EB_LIT - (int)(q3 >> 16) * KMr);                \
        float tl = rcpf((e0l + e1l) + (e2l + e3l));                                \
        float th = rcpf((e0h + e1h) + (e2h + e3h));                                \
        unsigned dm = minu2(Mn - pm, CLP2r);                                       \
        unsigned dr = minu2(Mn - (MrX), CLP2r);                                    \
        float fml = __int_as_float(EB_ONE - (int)(dm & 0xFFFFu) * KMr);            \
        float fmh = __int_as_float(EB_ONE - (int)(dm >> 16) * KMr);                \
        float frl = __int_as_float(EB_ONE - (int)(dr & 0xFFFFu) * KMr);            \
        float frh = __int_as_float(EB_ONE - (int)(dr >> 16) * KMr);                \
        Slo = fmaf(Slo, frl, fml * tl);                                            \
        Shi = fmaf(Shi, frh, fmh * th);                                            \
        MrX = Mn;                                                                  \
    }

// Kernel A (R9 grid, (256,4)). Fill is now a PURE COPY (LDG.128 -> STS.128):
// raw quanta in, renorm scale folded into KMr / decode constants.
__global__ __launch_bounds__(256, 4) void clause_kernel(int step) {
    __shared__ uint4 rows8[NG];   // 32 KB
    __shared__ float wmax[8];

    const int c  = blockIdx.z;
    const int bg = blockIdx.y;
    const int g0 = blockIdx.x * 256;
    const int tid = threadIdx.x;

    // Runtime exp slope / clamp / decode constants (uniform per kernel).
    float scP = 1.0f;
    if (step > 0) {
        const float mg = fdec(d_mG[step - 1]);
        scP = (mg > 1.0f) ? (1.0f / mg) : 1.0f;
    }
    const int KMr = __float2int_rn(KMF * scP);
    const int CLPr = (int)(1056964608.0f * rcpf((float)KMr)) - 1;  // (126<<23)/KMr, safe-low
    const unsigned CLP2r = (unsigned)CLPr | ((unsigned)CLPr << 16);
    const float DKC = INVQ * scP;                // Mn quanta -> value units

    // Fill: pure copy of packed rows.
    {
        const uint4* __restrict__ src = (step == 0)
            ? d_xq + (size_t)bg * NG
            : d_uq[(step - 1) & 1] + (size_t)(c * NBG + bg) * NG;
        for (int i = tid; i < NG; i += 256) rows8[i] = src[i];
    }
    __syncthreads();

    const int g = g0 + tid;
    const int lane = g & 31;
    const int4* __restrict__ ip = d_itr + ((size_t)(c * (NG/32) + (g >> 5)) * NS) * 32;

    uint4 Mr = make_uint4(0u, 0u, 0u, 0u);
    float S0 = 0.f, S1 = 0.f, S2 = 0.f, S3 = 0.f, S4 = 0.f, S5 = 0.f, S6 = 0.f, S7 = 0.f;

    int4 nxt = ip[lane];                       // s = 0, coalesced
    #pragma unroll
    for (int s = 0; s < NS; s++) {
        const int4 q = nxt;
        if (s < NS - 1) nxt = ip[(s + 1) * 32 + lane];
        const uint4 A  = rows8[q.x];
        const uint4 Bv = rows8[q.y];
        const uint4 Cv = rows8[q.z];
        const uint4 Dv = rows8[q.w];
        PAIR_UPD(A.x, Bv.x, Cv.x, Dv.x, Mr.x, S0, S1);
        PAIR_UPD(A.y, Bv.y, Cv.y, Dv.y, Mr.y, S2, S3);
        PAIR_UPD(A.z, Bv.z, Cv.z, Dv.z, Mr.z, S4, S5);
        PAIR_UPD(A.w, Bv.w, Cv.w, Dv.w, Mr.w, S6, S7);
    }

    // Decode r = Mn*scP/Q + gamma*ln(S); clamp at 0 for u16 re-encode.
    const float r0 = fmaxf(fmaf(GLN2, lg2f(S0), (float)(Mr.x & 0xFFFFu) * DKC), 0.f);
    const float r1 = fmaxf(fmaf(GLN2, lg2f(S1), (float)(Mr.x >> 16)     * DKC), 0.f);
    const float r2 = fmaxf(fmaf(GLN2, lg2f(S2), (float)(Mr.y & 0xFFFFu) * DKC), 0.f);
    const float r3 = fmaxf(fmaf(GLN2, lg2f(S3), (float)(Mr.y >> 16)     * DKC), 0.f);
    const float r4 = fmaxf(fmaf(GLN2, lg2f(S4), (float)(Mr.z & 0xFFFFu) * DKC), 0.f);
    const float r5 = fmaxf(fmaf(GLN2, lg2f(S5), (float)(Mr.z >> 16)     * DKC), 0.f);
    const float r6 = fmaxf(fmaf(GLN2, lg2f(S6), (float)(Mr.w & 0xFFFFu) * DKC), 0.f);
    const float r7 = fmaxf(fmaf(GLN2, lg2f(S7), (float)(Mr.w >> 16)     * DKC), 0.f);

    uint4 z;
    z.x = prmt(__float_as_uint(fmaf(r0, QF, MAGF)), __float_as_uint(fmaf(r1, QF, MAGF)), 0x5410u);
    z.y = prmt(__float_as_uint(fmaf(r2, QF, MAGF)), __float_as_uint(fmaf(r3, QF, MAGF)), 0x5410u);
    z.z = prmt(__float_as_uint(fmaf(r4, QF, MAGF)), __float_as_uint(fmaf(r5, QF, MAGF)), 0x5410u);
    z.w = prmt(__float_as_uint(fmaf(r6, QF, MAGF)), __float_as_uint(fmaf(r7, QF, MAGF)), 0x5410u);
    d_rq[(size_t)(c * NBG + bg) * NG + g] = z;

    float lmax = fmaxf(fmaxf(fmaxf(r0, r1), fmaxf(r2, r3)),
                       fmaxf(fmaxf(r4, r5), fmaxf(r6, r7)));

    #pragma unroll
    for (int o = 16; o > 0; o >>= 1) lmax = fmaxf(lmax, __shfl_xor_sync(0xffffffffu, lmax, o));
    if ((tid & 31) == 0) wmax[tid >> 5] = lmax;
    __syncthreads();
    if (tid == 0) {
        float m2 = wmax[0];
        #pragma unroll
        for (int w = 1; w < 8; w++) m2 = fmaxf(m2, wmax[w]);
        atomicMax(&d_mC[step * NC + c], fenc(m2));
    }
}

// Kernel B: one thread per (c, bgroup, g): softor2 of 8 quantized pairs.
__global__ __launch_bounds__(256) void combine_kernel(const float* __restrict__ x, int step) {
    __shared__ float wmax[8];
    const int tid = threadIdx.x;
    const int c   = blockIdx.x >> 6;
    const int bg  = (blockIdx.x >> 3) & 7;
    const int g   = (blockIdx.x & 7) * 256 + tid;
    const size_t idx = (size_t)(c * NBG + bg) * NG + g;

    const float mc = fdec(d_mC[step * NC + c]);
    const float kC = ((mc > 1.0f) ? (1.0f / mc) : 1.0f) * INVQ;
    const float cC = -MAGF * kC;

    float kP = INVQ, cP = -MAGF * INVQ;
    if (step > 0) {
        const float mg = fdec(d_mG[step - 1]);
        kP = ((mg > 1.0f) ? (1.0f / mg) : 1.0f) * INVQ;
        cP = -MAGF * kP;
    }

    const uint4 rq = d_rq[idx];
    uint4 aq;
    const float* __restrict__ xp = x + (size_t)(bg * 8) * NG + g;
    if (step > 0) aq = d_uq[(step - 1) & 1][idx];

    uint4 z;
    float lmax = -1e30f;
    #pragma unroll
    for (int w = 0; w < 4; w++) {
        const unsigned qr = (&rq.x)[w];
        const float rl = fmaf(dec_lo(qr), kC, cC);
        const float rh = fmaf(dec_hi(qr), kC, cC);
        float al, ah;
        if (step == 0) {
            al = xp[(2 * w) * NG];
            ah = xp[(2 * w + 1) * NG];
        } else {
            const unsigned qa = (&aq.x)[w];
            al = fmaf(dec_lo(qa), kP, cP);
            ah = fmaf(dec_hi(qa), kP, cP);
        }
        const float Ml = fmaxf(al, rl);
        const float Mh = fmaxf(ah, rh);
        const float ul = fmaf(GLN2, lg2f(1.0f + ex2f(-fabsf(al - rl) * KINV)), Ml);
        const float uh = fmaf(GLN2, lg2f(1.0f + ex2f(-fabsf(ah - rh) * KINV)), Mh);
        (&z.x)[w] = prmt(__float_as_uint(fmaf(ul, QF, MAGF)),
                         __float_as_uint(fmaf(uh, QF, MAGF)), 0x5410u);
        lmax = fmaxf(lmax, fmaxf(ul, uh));
    }
    d_uq[step & 1][idx] = z;

    #pragma unroll
    for (int o = 16; o > 0; o >>= 1) lmax = fmaxf(lmax, __shfl_xor_sync(0xffffffffu, lmax, o));
    if ((tid & 31) == 0) wmax[tid >> 5] = lmax;
    __syncthreads();
    if (tid == 0) {
        float m2 = wmax[0];
        #pragma unroll
        for (int w = 1; w < 8; w++) m2 = fmaxf(m2, wmax[w]);
        atomicMax(&d_mG[step], fenc(m2));
    }
}

// Final: decode packed u, apply global renorm, write float output.
__global__ __launch_bounds__(256) void final_kernel(float* __restrict__ out) {
    const int t  = blockIdx.x * 256 + threadIdx.x;
    const int g  = t & 2047;
    const int bg = (t >> 11) & 7;
    const int c  = t >> 14;
    const float mg = fdec(d_mG[NSTEPS - 1]);
    const float kF = ((mg > 1.0f) ? (1.0f / mg) : 1.0f) * INVQ;
    const float cF = -MAGF * kF;
    const uint4 q = d_uq[(NSTEPS - 1) & 1][t];
    float* __restrict__ op = out + (size_t)(c * NB + bg * 8) * NG + g;
    #pragma unroll
    for (int w = 0; w < 4; w++) {
        const unsigned qw = (&q.x)[w];
        op[(2 * w) * NG]     = fmaf(dec_lo(qw), kF, cF);
        op[(2 * w + 1) * NG] = fmaf(dec_hi(qw), kF, cF);
    }
}

extern "C" void kernel_launch(void* const* d_in, const int* in_sizes, int n_in,
                              void* d_out, int out_size) {
    const float* x = (const float*)d_in[0];   // (B, G) float32
    const int*   I = (const int*)d_in[1];     // (C, G, S, L) int32

    transpose_I_kernel<<<(NC * NG * NS) / 256, 256>>>(I, x);

    dim3 gridA(NG / 256, NBG, NC);            // (8, 8, 16) = 1024 blocks
    for (int t = 0; t < NSTEPS; t++) {
        clause_kernel<<<gridA, 256>>>(t);
        combine_kernel<<<NPK / 256, 256>>>(x, t);
    }
    final_kernel<<<NPK / 256, 256>>>((float*)d_out);
}

// round 16
// speedup vs baseline: 1.0551x; 1.0551x over previous
#include <cuda_runtime.h>

// Problem constants: C=16, B=64, G=2048, S=8, L=4, infer_step=3.
#define NC 16
#define NB 64
#define NG 2048
#define NS 8
#define NL 4
#define NSTEPS 3
#define GAMMA 0.001f
#define KINV  1442.6950408889634f   /* 1000 * log2(e) */
#define GLN2  6.931471805599453e-4f /* gamma * ln(2)  */
#define BG (NB*NG)            // 131072
#define TOT (NC*NB*NG)        // 2097152
#define NBG (NB/8)            // 8 b-groups
#define NPK (NC*NBG*NG)       // 262144 packed uint4 per tensor

// u16 quantization: q = round(v * QF), v in [0,~1.003].
#define QF    61440.0f
#define INVQ  (1.0f/61440.0f)
#define MAGF  12582912.0f           /* 1.5*2^23 */
#define MAGI  0x4B400000u
#define KM    196976                /* round(KINV * 2^23 / QF) */
#define CLP   5365                  /* floor((126<<23)/KM) */
#define CLP2  ((CLP) | ((CLP) << 16))
#define EB_LIT 1065056216           /* (127<<23) - 297000 (minimax bias) */
#define EB_ONE 1065353216           /* (127<<23) */

// Scratch. Packed-u16 interchange: uint4 at [(c*8+bg)*NG+g] = rows 8bg..8bg+7
// at column g; word w = rows (2w lo16, 2w+1 hi16).
__device__ uint4 d_rq[NPK];          // 4 MB: raw clause softor, quantized
__device__ uint4 d_uq[2][NPK];       // 2x 4 MB: combined valuations, quantized
__device__ int4  d_itr[NC * (NG/32) * NS * 32];   // transposed indices, 4MB
__device__ unsigned d_mC[NSTEPS * NC];
__device__ unsigned d_mG[NSTEPS];

__device__ __forceinline__ float ex2f(float x) { float y; asm("ex2.approx.f32 %0, %1;" : "=f"(y) : "f"(x)); return y; }
__device__ __forceinline__ float lg2f(float x) { float y; asm("lg2.approx.f32 %0, %1;" : "=f"(y) : "f"(x)); return y; }
__device__ __forceinline__ float rcpf(float x) { float y; asm("rcp.approx.f32 %0, %1;" : "=f"(y) : "f"(x)); return y; }
__device__ __forceinline__ unsigned minu2(unsigned a, unsigned b) {
    unsigned d; asm("min.u16x2 %0, %1, %2;" : "=r"(d) : "r"(a), "r"(b)); return d;
}
__device__ __forceinline__ unsigned maxu2(unsigned a, unsigned b) {
    unsigned d; asm("max.u16x2 %0, %1, %2;" : "=r"(d) : "r"(a), "r"(b)); return d;
}
__device__ __forceinline__ unsigned prmt(unsigned a, unsigned b, unsigned c) {
    unsigned d; asm("prmt.b32 %0, %1, %2, %3;" : "=r"(d) : "r"(a), "r"(b), "r"(c)); return d;
}
// Warp-wide max in one instruction (sm_80+).
__device__ __forceinline__ unsigned redux_max(unsigned v) {
    unsigned d; asm("redux.sync.max.u32 %0, %1, 0xffffffff;" : "=r"(d) : "r"(v)); return d;
}
__device__ __forceinline__ float dec_lo(unsigned q) {
    return __uint_as_float(prmt(q, MAGI, 0x7610u));
}
__device__ __forceinline__ float dec_hi(unsigned q) {
    return __uint_as_float(prmt(q, MAGI, 0x7632u));
}

// Order-preserving float<->uint encoding for atomicMax / redux.
__device__ __forceinline__ unsigned fenc(float f) {
    unsigned u = __float_as_uint(f);
    return (u & 0x80000000u) ? ~u : (u | 0x80000000u);
}
__device__ __forceinline__ float fdec(unsigned u) {
    return __uint_as_float((u & 0x80000000u) ? (u ^ 0x80000000u) : ~u);
}

// One-time transpose of I for coalesced hot-loop index loads (+ max init).
__global__ __launch_bounds__(256) void transpose_I_kernel(const int* __restrict__ I) {
    const int t  = blockIdx.x * 256 + threadIdx.x;
    if (blockIdx.x == 0 && threadIdx.x < 64) {
        if (threadIdx.x < NSTEPS * NC) d_mC[threadIdx.x] = 0u;
        if (threadIdx.x < NSTEPS)      d_mG[threadIdx.x] = 0u;
    }
    const int gl = t & 31;
    const int s  = (t >> 5) & 7;
    const int gb = (t >> 8) & 63;
    const int c  = t >> 14;
    const int4* __restrict__ in = reinterpret_cast<const int4*>(I);
    d_itr[t] = in[((size_t)(c * NG + gb * 32 + gl)) * NS + s];
}

// Packed-pair softand + streaming-softor for rows (2j, 2j+1). (Proven R9/R13.)
// u16x2 diffs are half-wise non-negative -> 32-bit sub is exact SIMD sub.
// Exps via integer exponent injection (IMAD on FMA pipe); only rcp on MUFU.
#define PAIR_UPD(La, Lb, Lc, Ld, MrX, Slo, Shi)                                    \
    {                                                                              \
        unsigned pm = minu2(minu2(La, Lb), minu2(Lc, Ld));                         \
        unsigned Mn = maxu2(MrX, pm);                                              \
        unsigned q0 = minu2((La) - pm, CLP2);                                      \
        unsigned q1 = minu2((Lb) - pm, CLP2);                                      \
        unsigned q2 = minu2((Lc) - pm, CLP2);                                      \
        unsigned q3 = minu2((Ld) - pm, CLP2);                                      \
        float e0l = __int_as_float(EB_LIT - (int)(q0 & 0xFFFFu) * KM);             \
        float e1l = __int_as_float(EB_LIT - (int)(q1 & 0xFFFFu) * KM);             \
        float e2l = __int_as_float(EB_LIT - (int)(q2 & 0xFFFFu) * KM);             \
        float e3l = __int_as_float(EB_LIT - (int)(q3 & 0xFFFFu) * KM);             \
        float e0h = __int_as_float(EB_LIT - (int)(q0 >> 16) * KM);                 \
        float e1h = __int_as_float(EB_LIT - (int)(q1 >> 16) * KM);                 \
        float e2h = __int_as_float(EB_LIT - (int)(q2 >> 16) * KM);                 \
        float e3h = __int_as_float(EB_LIT - (int)(q3 >> 16) * KM);                 \
        float tl = rcpf((e0l + e1l) + (e2l + e3l));                                \
        float th = rcpf((e0h + e1h) + (e2h + e3h));                                \
        unsigned dm = minu2(Mn - pm, CLP2);                                        \
        unsigned dr = minu2(Mn - (MrX), CLP2);                                     \
        float fml = __int_as_float(EB_ONE - (int)(dm & 0xFFFFu) * KM);             \
        float fmh = __int_as_float(EB_ONE - (int)(dm >> 16) * KM);                 \
        float frl = __int_as_float(EB_ONE - (int)(dr & 0xFFFFu) * KM);             \
        float frh = __int_as_float(EB_ONE - (int)(dr >> 16) * KM);                 \
        Slo = fmaf(Slo, frl, fml * tl);                                            \
        Shi = fmaf(Shi, frh, fmh * th);                                            \
        MrX = Mn;                                                                  \
    }

// Kernel A (R9 grid, (256,4)): 8 rows packed u16 in uint4; one LDS.128 per
// gathered index serves all 8 rows; packed uint4 epilogue store.
__global__ __launch_bounds__(256, 4) void clause_kernel(const float* __restrict__ x,
                                                        int step) {
    __shared__ uint4 rows8[NG];   // 32 KB
    __shared__ unsigned wmax[8];

    const int c  = blockIdx.z;
    const int bg = blockIdx.y;
    const int b0 = bg * 8;
    const int g0 = blockIdx.x * 256;
    const int tid = threadIdx.x;

    if (step == 0) {
        const float* __restrict__ vp = x + (size_t)b0 * NG;
        for (int i = tid; i < NG; i += 256) {
            uint4 z;
            #pragma unroll
            for (int j = 0; j < 4; j++) {
                unsigned a = __float_as_uint(fmaf(vp[(2 * j) * NG + i],     QF, MAGF));
                unsigned b = __float_as_uint(fmaf(vp[(2 * j + 1) * NG + i], QF, MAGF));
                (&z.x)[j] = prmt(a, b, 0x5410u);
            }
            rows8[i] = z;
        }
    } else {
        const float mg = fdec(d_mG[step - 1]);
        const float sc = (mg > 1.0f) ? (1.0f / mg) : 1.0f;
        const float c1 = MAGF - MAGF * sc;
        const uint4* __restrict__ up = d_uq[(step - 1) & 1] + (size_t)(c * NBG + bg) * NG;
        for (int i = tid; i < NG; i += 256) {
            uint4 q = up[i];
            uint4 z;
            #pragma unroll
            for (int j = 0; j < 4; j++) {
                unsigned w = (&q.x)[j];
                unsigned a = __float_as_uint(fmaf(dec_lo(w), sc, c1));
                unsigned b = __float_as_uint(fmaf(dec_hi(w), sc, c1));
                (&z.x)[j] = prmt(a, b, 0x5410u);
            }
            rows8[i] = z;
        }
    }
    __syncthreads();

    const int g = g0 + tid;
    const int lane = g & 31;
    const int4* __restrict__ ip = d_itr + ((size_t)(c * (NG/32) + (g >> 5)) * NS) * 32;

    uint4 Mr = make_uint4(0u, 0u, 0u, 0u);
    float S0 = 0.f, S1 = 0.f, S2 = 0.f, S3 = 0.f, S4 = 0.f, S5 = 0.f, S6 = 0.f, S7 = 0.f;

    int4 nxt = ip[lane];
    #pragma unroll
    for (int s = 0; s < NS; s++) {
        const int4 q = nxt;
        if (s < NS - 1) nxt = ip[(s + 1) * 32 + lane];
        const uint4 A  = rows8[q.x];
        const uint4 Bv = rows8[q.y];
        const uint4 Cv = rows8[q.z];
        const uint4 Dv = rows8[q.w];
        PAIR_UPD(A.x, Bv.x, Cv.x, Dv.x, Mr.x, S0, S1);
        PAIR_UPD(A.y, Bv.y, Cv.y, Dv.y, Mr.y, S2, S3);
        PAIR_UPD(A.z, Bv.z, Cv.z, Dv.z, Mr.z, S4, S5);
        PAIR_UPD(A.w, Bv.w, Cv.w, Dv.w, Mr.w, S6, S7);
    }

    // Decode r = Mn/Q + gamma*ln(S); clamp at 0 for u16 re-encode.
    const float r0 = fmaxf(fmaf(GLN2, lg2f(S0), (float)(Mr.x & 0xFFFFu) * INVQ), 0.f);
    const float r1 = fmaxf(fmaf(GLN2, lg2f(S1), (float)(Mr.x >> 16)     * INVQ), 0.f);
    const float r2 = fmaxf(fmaf(GLN2, lg2f(S2), (float)(Mr.y & 0xFFFFu) * INVQ), 0.f);
    const float r3 = fmaxf(fmaf(GLN2, lg2f(S3), (float)(Mr.y >> 16)     * INVQ), 0.f);
    const float r4 = fmaxf(fmaf(GLN2, lg2f(S4), (float)(Mr.z & 0xFFFFu) * INVQ), 0.f);
    const float r5 = fmaxf(fmaf(GLN2, lg2f(S5), (float)(Mr.z >> 16)     * INVQ), 0.f);
    const float r6 = fmaxf(fmaf(GLN2, lg2f(S6), (float)(Mr.w & 0xFFFFu) * INVQ), 0.f);
    const float r7 = fmaxf(fmaf(GLN2, lg2f(S7), (float)(Mr.w >> 16)     * INVQ), 0.f);

    uint4 z;
    z.x = prmt(__float_as_uint(fmaf(r0, QF, MAGF)), __float_as_uint(fmaf(r1, QF, MAGF)), 0x5410u);
    z.y = prmt(__float_as_uint(fmaf(r2, QF, MAGF)), __float_as_uint(fmaf(r3, QF, MAGF)), 0x5410u);
    z.z = prmt(__float_as_uint(fmaf(r4, QF, MAGF)), __float_as_uint(fmaf(r5, QF, MAGF)), 0x5410u);
    z.w = prmt(__float_as_uint(fmaf(r6, QF, MAGF)), __float_as_uint(fmaf(r7, QF, MAGF)), 0x5410u);
    d_rq[(size_t)(c * NBG + bg) * NG + g] = z;

    float lmax = fmaxf(fmaxf(fmaxf(r0, r1), fmaxf(r2, r3)),
                       fmaxf(fmaxf(r4, r5), fmaxf(r6, r7)));

    // Block max via redux (1 inst/warp) -> per-clause atomic max.
    const unsigned wm = redux_max(fenc(lmax));
    if ((tid & 31) == 0) wmax[tid >> 5] = wm;
    __syncthreads();
    if (tid == 0) {
        unsigned m2 = wmax[0];
        #pragma unroll
        for (int w = 1; w < 8; w++) m2 = max(m2, wmax[w]);
        atomicMax(&d_mC[step * NC + c], m2);
    }
}

// Kernel B: one thread per (c, bgroup, g): decodes 8 quantized r's + 8 prev
// u's (2 LDG.128), softor2 each, re-encodes 8 u's (1 STG.128).
__global__ __launch_bounds__(256) void combine_kernel(const float* __restrict__ x, int step) {
    __shared__ unsigned wmax[8];
    const int tid = threadIdx.x;
    const int c   = blockIdx.x >> 6;
    const int bg  = (blockIdx.x >> 3) & 7;
    const int g   = (blockIdx.x & 7) * 256 + tid;
    const size_t idx = (size_t)(c * NBG + bg) * NG + g;

    const float mc = fdec(d_mC[step * NC + c]);
    const float kC = ((mc > 1.0f) ? (1.0f / mc) : 1.0f) * INVQ;
    const float cC = -MAGF * kC;

    float kP = INVQ, cP = -MAGF * INVQ;
    if (step > 0) {
        const float mg = fdec(d_mG[step - 1]);
        kP = ((mg > 1.0f) ? (1.0f / mg) : 1.0f) * INVQ;
        cP = -MAGF * kP;
    }

    const uint4 rq = d_rq[idx];
    uint4 aq;
    const float* __restrict__ xp = x + (size_t)(bg * 8) * NG + g;
    if (step > 0) aq = d_uq[(step - 1) & 1][idx];

    uint4 z;
    float lmax = -1e30f;
    #pragma unroll
    for (int w = 0; w < 4; w++) {
        const unsigned qr = (&rq.x)[w];
        const float rl = fmaf(dec_lo(qr), kC, cC);
        const float rh = fmaf(dec_hi(qr), kC, cC);
        float al, ah;
        if (step == 0) {
            al = xp[(2 * w) * NG];
            ah = xp[(2 * w + 1) * NG];
        } else {
            const unsigned qa = (&aq.x)[w];
            al = fmaf(dec_lo(qa), kP, cP);
            ah = fmaf(dec_hi(qa), kP, cP);
        }
        const float Ml = fmaxf(al, rl);
        const float Mh = fmaxf(ah, rh);
        const float ul = fmaf(GLN2, lg2f(1.0f + ex2f(-fabsf(al - rl) * KINV)), Ml);
        const float uh = fmaf(GLN2, lg2f(1.0f + ex2f(-fabsf(ah - rh) * KINV)), Mh);
        (&z.x)[w] = prmt(__float_as_uint(fmaf(ul, QF, MAGF)),
                         __float_as_uint(fmaf(uh, QF, MAGF)), 0x5410u);
        lmax = fmaxf(lmax, fmaxf(ul, uh));
    }
    d_uq[step & 1][idx] = z;

    const unsigned wm = redux_max(fenc(lmax));
    if ((tid & 31) == 0) wmax[tid >> 5] = wm;
    __syncthreads();
    if (tid == 0) {
        unsigned m2 = wmax[0];
        #pragma unroll
        for (int w = 1; w < 8; w++) m2 = max(m2, wmax[w]);
        atomicMax(&d_mG[step], m2);
    }
}

// Final: decode packed u, apply global renorm, write float output.
__global__ __launch_bounds__(256) void final_kernel(float* __restrict__ out) {
    const int t  = blockIdx.x * 256 + threadIdx.x;
    const int g  = t & 2047;
    const int bg = (t >> 11) & 7;
    const int c  = t >> 14;
    const float mg = fdec(d_mG[NSTEPS - 1]);
    const float kF = ((mg > 1.0f) ? (1.0f / mg) : 1.0f) * INVQ;
    const float cF = -MAGF * kF;
    const uint4 q = d_uq[(NSTEPS - 1) & 1][t];
    float* __restrict__ op = out + (size_t)(c * NB + bg * 8) * NG + g;
    #pragma unroll
    for (int w = 0; w < 4; w++) {
        const unsigned qw = (&q.x)[w];
        op[(2 * w) * NG]     = fmaf(dec_lo(qw), kF, cF);
        op[(2 * w + 1) * NG] = fmaf(dec_hi(qw), kF, cF);
    }
}

extern "C" void kernel_launch(void* const* d_in, const int* in_sizes, int n_in,
                              void* d_out, int out_size) {
    const float* x = (const float*)d_in[0];   // (B, G) float32
    const int*   I = (const int*)d_in[1];     // (C, G, S, L) int32

    transpose_I_kernel<<<(NC * NG * NS) / 256, 256>>>(I);

    dim3 gridA(NG / 256, NBG, NC);            // (8, 8, 16) = 1024 blocks
    for (int t = 0; t < NSTEPS; t++) {
        clause_kernel<<<gridA, 256>>>(x, t);
        combine_kernel<<<NPK / 256, 256>>>(x, t);
    }
    final_kernel<<<NPK / 256, 256>>>((float*)d_out);
}

// round 17
// speedup vs baseline: 1.3358x; 1.2660x over previous
#include <cuda_runtime.h>
#include <cuda_fp16.h>

// Problem constants: C=16, B=64, G=2048, S=8, L=4, infer_step=3.
#define NC 16
#define NB 64
#define NG 2048
#define NS 8
#define NL 4
#define NSTEPS 3
#define GAMMA 0.001f
#define KINV  1442.6950408889634f   /* 1000 * log2(e) */
#define GLN2  6.931471805599453e-4f /* gamma * ln(2)  */
#define BG (NB*NG)
#define TOT (NC*NB*NG)
#define NBG (NB/8)
#define NPK (NC*NBG*NG)

// u16 quantization: q = round(v * QF), v in [0,~1.003].
#define QF    61440.0f
#define INVQ  (1.0f/61440.0f)
#define MAGF  12582912.0f           /* 1.5*2^23 */
#define MAGI  0x4B400000u
#define KMF16 24.044917f            /* (KINV/QF)*1024: fp16 exp bits per quantum */
// fp16x2 exponent-injection constants (per-half fields).
#define EB2_LIT 0x3B9C3B9Cu         /* 15260 each: 1.0 biased -36 (minimax) */
#define EB2_ONE 0x3C003C00u         /* 15360 each: exact 1.0 */
#define EB16_LO 15260               /* lo field of EB2_LIT: clamp bound */
#define RCPK2   0x77A477A4u         /* fp16 rcp bit-complement magic, packed */
#define TWO2    0x40004000u         /* 2.0 packed */
#define NEG2    0x80008000u         /* sign-bit mask packed */

// Scratch. Packed-u16 interchange: uint4 at [(c*8+bg)*NG+g] = rows 8bg..8bg+7
// at column g; word w = rows (2w lo16, 2w+1 hi16).
__device__ uint4 d_rq[NPK];
__device__ uint4 d_uq[2][NPK];
__device__ int4  d_itr[NC * (NG/32) * NS * 32];
__device__ unsigned d_mC[NSTEPS * NC];
__device__ unsigned d_mG[NSTEPS];

__device__ __forceinline__ float ex2f(float x) { float y; asm("ex2.approx.f32 %0, %1;" : "=f"(y) : "f"(x)); return y; }
__device__ __forceinline__ float lg2f(float x) { float y; asm("lg2.approx.f32 %0, %1;" : "=f"(y) : "f"(x)); return y; }
__device__ __forceinline__ unsigned minu2(unsigned a, unsigned b) {
    unsigned d; asm("min.u16x2 %0, %1, %2;" : "=r"(d) : "r"(a), "r"(b)); return d;
}
__device__ __forceinline__ unsigned maxu2(unsigned a, unsigned b) {
    unsigned d; asm("max.u16x2 %0, %1, %2;" : "=r"(d) : "r"(a), "r"(b)); return d;
}
__device__ __forceinline__ unsigned prmt(unsigned a, unsigned b, unsigned c) {
    unsigned d; asm("prmt.b32 %0, %1, %2, %3;" : "=r"(d) : "r"(a), "r"(b), "r"(c)); return d;
}
__device__ __forceinline__ unsigned hadd2u(unsigned a, unsigned b) {
    unsigned d; asm("add.rn.f16x2 %0, %1, %2;" : "=r"(d) : "r"(a), "r"(b)); return d;
}
__device__ __forceinline__ unsigned hmul2u(unsigned a, unsigned b) {
    unsigned d; asm("mul.rn.f16x2 %0, %1, %2;" : "=r"(d) : "r"(a), "r"(b)); return d;
}
__device__ __forceinline__ unsigned hfma2u(unsigned a, unsigned b, unsigned c) {
    unsigned d; asm("fma.rn.f16x2 %0, %1, %2, %3;" : "=r"(d) : "r"(a), "r"(b), "r"(c)); return d;
}
__device__ __forceinline__ unsigned redux_max(unsigned v) {
    unsigned d; asm("redux.sync.max.u32 %0, %1, 0xffffffff;" : "=r"(d) : "r"(v)); return d;
}
__device__ __forceinline__ float dec_lo(unsigned q) {
    return __uint_as_float(prmt(q, MAGI, 0x7610u));
}
__device__ __forceinline__ float dec_hi(unsigned q) {
    return __uint_as_float(prmt(q, MAGI, 0x7632u));
}
__device__ __forceinline__ unsigned fenc(float f) {
    unsigned u = __float_as_uint(f);
    return (u & 0x80000000u) ? ~u : (u | 0x80000000u);
}
__device__ __forceinline__ float fdec(unsigned u) {
    return __uint_as_float((u & 0x80000000u) ? (u ^ 0x80000000u) : ~u);
}

// One-time transpose of I (+ max init).
__global__ __launch_bounds__(256) void transpose_I_kernel(const int* __restrict__ I) {
    const int t  = blockIdx.x * 256 + threadIdx.x;
    if (blockIdx.x == 0 && threadIdx.x < 64) {
        if (threadIdx.x < NSTEPS * NC) d_mC[threadIdx.x] = 0u;
        if (threadIdx.x < NSTEPS)      d_mG[threadIdx.x] = 0u;
    }
    const int gl = t & 31;
    const int s  = (t >> 5) & 7;
    const int gb = (t >> 8) & 63;
    const int c  = t >> 14;
    const int4* __restrict__ in = reinterpret_cast<const int4*>(I);
    d_itr[t] = in[((size_t)(c * NG + gb * 32 + gl)) * NS + s];
}

// Packed-fp16 softand + streaming softor for rows (2j, 2j+1).
// term = fm/d, d = sum_l exp(-(v_l - pm)K), fm = exp(-(Mn - pm)K);
// rescale fr = exp(-(Mn - Mr_old)K). All exps via ONE IMAD into fp16x2
// bit-fields (both halves at once, borrow-free: clamp CLPr = 15260/KMr keeps
// every 16-bit field non-negative — the R15 bug was CLPr too large, letting
// the lo field underflow and borrow into the hi half). Reciprocal via fp16
// bit-complement + 1 Newton step; no MUFU in the loop.
#define PAIR_UPD(La, Lb, Lc, Ld, MrX, Sr)                                          \
    {                                                                              \
        unsigned pm = minu2(minu2(La, Lb), minu2(Lc, Ld));                         \
        unsigned Mn = maxu2(MrX, pm);                                              \
        unsigned q0 = minu2((La) - pm, CLP2r);                                     \
        unsigned q1 = minu2((Lb) - pm, CLP2r);                                     \
        unsigned q2 = minu2((Lc) - pm, CLP2r);                                     \
        unsigned q3 = minu2((Ld) - pm, CLP2r);                                     \
        unsigned e0 = EB2_LIT - q0 * KMru;                                         \
        unsigned e1 = EB2_LIT - q1 * KMru;                                         \
        unsigned e2 = EB2_LIT - q2 * KMru;                                         \
        unsigned e3 = EB2_LIT - q3 * KMru;                                         \
        unsigned d2 = hadd2u(hadd2u(e0, e1), hadd2u(e2, e3));                      \
        unsigned t0 = RCPK2 - d2;                                                  \
        unsigned w_ = hfma2u(d2 ^ NEG2, t0, TWO2);                                 \
        unsigned t1 = hmul2u(t0, w_);                                              \
        unsigned dm = minu2(Mn - pm, CLP2r);                                       \
        unsigned dr = minu2(Mn - (MrX), CLP2r);                                    \
        unsigned fm = EB2_ONE - dm * KMru;                                         \
        unsigned fr = EB2_ONE - dr * KMru;                                         \
        Sr = hfma2u(Sr, fr, hmul2u(fm, t1));                                       \
        MrX = Mn;                                                                  \
    }

// Kernel A (R9 grid, (256,4)): 8 rows packed u16 in uint4; one LDS.128 per
// gathered index serves all 8 rows; packed uint4 epilogue store.
__global__ __launch_bounds__(256, 4) void clause_kernel(const float* __restrict__ x,
                                                        int step) {
    __shared__ uint4 rows8[NG];   // 32 KB
    __shared__ unsigned wmax[8];

    const int c  = blockIdx.z;
    const int bg = blockIdx.y;
    const int b0 = bg * 8;
    const int g0 = blockIdx.x * 256;
    const int tid = threadIdx.x;

    // Runtime slope/clamp (renorm scale folded into the fp16 exp slope).
    float scP = 1.0f;
    if (step > 0) {
        const float mg = fdec(d_mG[step - 1]);
        scP = (mg > 1.0f) ? (1.0f / mg) : 1.0f;
    }
    const unsigned KMru = (unsigned)__float2int_rn(KMF16 * scP);
    const unsigned CLPr = (unsigned)(EB16_LO) / KMru;   // borrow-free clamp
    const unsigned CLP2r = CLPr | (CLPr << 16);
    const float DKC = INVQ;   // Mn quanta -> value units (row quanta already scaled)

    // Fill: quantize/rescale 8 rows to u16, pack pairs.
    if (step == 0) {
        const float* __restrict__ vp = x + (size_t)b0 * NG;
        for (int i = tid; i < NG; i += 256) {
            uint4 z;
            #pragma unroll
            for (int j = 0; j < 4; j++) {
                unsigned a = __float_as_uint(fmaf(vp[(2 * j) * NG + i],     QF, MAGF));
                unsigned b = __float_as_uint(fmaf(vp[(2 * j + 1) * NG + i], QF, MAGF));
                (&z.x)[j] = prmt(a, b, 0x5410u);
            }
            rows8[i] = z;
        }
    } else {
        const float sc = scP;
        const float c1 = MAGF - MAGF * sc;
        const uint4* __restrict__ up = d_uq[(step - 1) & 1] + (size_t)(c * NBG + bg) * NG;
        for (int i = tid; i < NG; i += 256) {
            uint4 q = up[i];
            uint4 z;
            #pragma unroll
            for (int j = 0; j < 4; j++) {
                unsigned w = (&q.x)[j];
                unsigned a = __float_as_uint(fmaf(dec_lo(w), sc, c1));
                unsigned b = __float_as_uint(fmaf(dec_hi(w), sc, c1));
                (&z.x)[j] = prmt(a, b, 0x5410u);
            }
            rows8[i] = z;
        }
    }
    __syncthreads();

    // Rows are now pre-scaled quanta -> base slope at runtime stays KINV/QF;
    // recompute slope WITHOUT scP (values already rescaled in the fill).
    const unsigned KMu2 = (unsigned)__float2int_rn(KMF16);
    const unsigned CLPb = (unsigned)(EB16_LO) / KMu2;
    const unsigned CLPb2 = CLPb | (CLPb << 16);
    (void)KMru; (void)CLP2r;
    #undef  KMru
    #undef  CLP2r
    #define KMru  KMu2
    #define CLP2r CLPb2

    const int g = g0 + tid;
    const int lane = g & 31;
    const int4* __restrict__ ip = d_itr + ((size_t)(c * (NG/32) + (g >> 5)) * NS) * 32;

    uint4 Mr = make_uint4(0u, 0u, 0u, 0u);
    unsigned S0 = 0u, S1 = 0u, S2 = 0u, S3 = 0u;   // half2 accumulators

    int4 nxt = ip[lane];
    #pragma unroll
    for (int s = 0; s < NS; s++) {
        const int4 q = nxt;
        if (s < NS - 1) nxt = ip[(s + 1) * 32 + lane];
        const uint4 A  = rows8[q.x];
        const uint4 Bv = rows8[q.y];
        const uint4 Cv = rows8[q.z];
        const uint4 Dv = rows8[q.w];
        PAIR_UPD(A.x, Bv.x, Cv.x, Dv.x, Mr.x, S0);
        PAIR_UPD(A.y, Bv.y, Cv.y, Dv.y, Mr.y, S1);
        PAIR_UPD(A.z, Bv.z, Cv.z, Dv.z, Mr.z, S2);
        PAIR_UPD(A.w, Bv.w, Cv.w, Dv.w, Mr.w, S3);
    }
    #undef  KMru
    #undef  CLP2r

    // Decode r = Mn/Q + gamma*ln(S); clamp at 0 for u16 re-encode.
    const __half2 h0 = *reinterpret_cast<const __half2*>(&S0);
    const __half2 h1 = *reinterpret_cast<const __half2*>(&S1);
    const __half2 h2 = *reinterpret_cast<const __half2*>(&S2);
    const __half2 h3 = *reinterpret_cast<const __half2*>(&S3);
    const float r0 = fmaxf(fmaf(GLN2, lg2f(__low2float(h0)),  (float)(Mr.x & 0xFFFFu) * DKC), 0.f);
    const float r1 = fmaxf(fmaf(GLN2, lg2f(__high2float(h0)), (float)(Mr.x >> 16)     * DKC), 0.f);
    const float r2 = fmaxf(fmaf(GLN2, lg2f(__low2float(h1)),  (float)(Mr.y & 0xFFFFu) * DKC), 0.f);
    const float r3 = fmaxf(fmaf(GLN2, lg2f(__high2float(h1)), (float)(Mr.y >> 16)     * DKC), 0.f);
    const float r4 = fmaxf(fmaf(GLN2, lg2f(__low2float(h2)),  (float)(Mr.z & 0xFFFFu) * DKC), 0.f);
    const float r5 = fmaxf(fmaf(GLN2, lg2f(__high2float(h2)), (float)(Mr.z >> 16)     * DKC), 0.f);
    const float r6 = fmaxf(fmaf(GLN2, lg2f(__low2float(h3)),  (float)(Mr.w & 0xFFFFu) * DKC), 0.f);
    const float r7 = fmaxf(fmaf(GLN2, lg2f(__high2float(h3)), (float)(Mr.w >> 16)     * DKC), 0.f);

    uint4 z;
    z.x = prmt(__float_as_uint(fmaf(r0, QF, MAGF)), __float_as_uint(fmaf(r1, QF, MAGF)), 0x5410u);
    z.y = prmt(__float_as_uint(fmaf(r2, QF, MAGF)), __float_as_uint(fmaf(r3, QF, MAGF)), 0x5410u);
    z.z = prmt(__float_as_uint(fmaf(r4, QF, MAGF)), __float_as_uint(fmaf(r5, QF, MAGF)), 0x5410u);
    z.w = prmt(__float_as_uint(fmaf(r6, QF, MAGF)), __float_as_uint(fmaf(r7, QF, MAGF)), 0x5410u);
    d_rq[(size_t)(c * NBG + bg) * NG + g] = z;

    float lmax = fmaxf(fmaxf(fmaxf(r0, r1), fmaxf(r2, r3)),
                       fmaxf(fmaxf(r4, r5), fmaxf(r6, r7)));

    const unsigned wm = redux_max(fenc(lmax));
    if ((tid & 31) == 0) wmax[tid >> 5] = wm;
    __syncthreads();
    if (tid == 0) {
        unsigned m2 = wmax[0];
        #pragma unroll
        for (int w = 1; w < 8; w++) m2 = max(m2, wmax[w]);
        atomicMax(&d_mC[step * NC + c], m2);
    }
}

// Kernel B: one thread per (c, bgroup, g): softor2 of 8 quantized pairs.
__global__ __launch_bounds__(256) void combine_kernel(const float* __restrict__ x, int step) {
    __shared__ unsigned wmax[8];
    const int tid = threadIdx.x;
    const int c   = blockIdx.x >> 6;
    const int bg  = (blockIdx.x >> 3) & 7;
    const int g   = (blockIdx.x & 7) * 256 + tid;
    const size_t idx = (size_t)(c * NBG + bg) * NG + g;

    const float mc = fdec(d_mC[step * NC + c]);
    const float kC = ((mc > 1.0f) ? (1.0f / mc) : 1.0f) * INVQ;
    const float cC = -MAGF * kC;

    float kP = INVQ, cP = -MAGF * INVQ;
    if (step > 0) {
        const float mg = fdec(d_mG[step - 1]);
        kP = ((mg > 1.0f) ? (1.0f / mg) : 1.0f) * INVQ;
        cP = -MAGF * kP;
    }

    const uint4 rq = d_rq[idx];
    uint4 aq;
    const float* __restrict__ xp = x + (size_t)(bg * 8) * NG + g;
    if (step > 0) aq = d_uq[(step - 1) & 1][idx];

    uint4 z;
    float lmax = -1e30f;
    #pragma unroll
    for (int w = 0; w < 4; w++) {
        const unsigned qr = (&rq.x)[w];
        const float rl = fmaf(dec_lo(qr), kC, cC);
        const float rh = fmaf(dec_hi(qr), kC, cC);
        float al, ah;
        if (step == 0) {
            al = xp[(2 * w) * NG];
            ah = xp[(2 * w + 1) * NG];
        } else {
            const unsigned qa = (&aq.x)[w];
            al = fmaf(dec_lo(qa), kP, cP);
            ah = fmaf(dec_hi(qa), kP, cP);
        }
        const float Ml = fmaxf(al, rl);
        const float Mh = fmaxf(ah, rh);
        const float ul = fmaf(GLN2, lg2f(1.0f + ex2f(-fabsf(al - rl) * KINV)), Ml);
        const float uh = fmaf(GLN2, lg2f(1.0f + ex2f(-fabsf(ah - rh) * KINV)), Mh);
        (&z.x)[w] = prmt(__float_as_uint(fmaf(ul, QF, MAGF)),
                         __float_as_uint(fmaf(uh, QF, MAGF)), 0x5410u);
        lmax = fmaxf(lmax, fmaxf(ul, uh));
    }
    d_uq[step & 1][idx] = z;

    const unsigned wm = redux_max(fenc(lmax));
    if ((tid & 31) == 0) wmax[tid >> 5] = wm;
    __syncthreads();
    if (tid == 0) {
        unsigned m2 = wmax[0];
        #pragma unroll
        for (int w = 1; w < 8; w++) m2 = max(m2, wmax[w]);
        atomicMax(&d_mG[step], m2);
    }
}

// Final: decode packed u, apply global renorm, write float output.
__global__ __launch_bounds__(256) void final_kernel(float* __restrict__ out) {
    const int t  = blockIdx.x * 256 + threadIdx.x;
    const int g  = t & 2047;
    const int bg = (t >> 11) & 7;
    const int c  = t >> 14;
    const float mg = fdec(d_mG[NSTEPS - 1]);
    const float kF = ((mg > 1.0f) ? (1.0f / mg) : 1.0f) * INVQ;
    const float cF = -MAGF * kF;
    const uint4 q = d_uq[(NSTEPS - 1) & 1][t];
    float* __restrict__ op = out + (size_t)(c * NB + bg * 8) * NG + g;
    #pragma unroll
    for (int w = 0; w < 4; w++) {
        const unsigned qw = (&q.x)[w];
        op[(2 * w) * NG]     = fmaf(dec_lo(qw), kF, cF);
        op[(2 * w + 1) * NG] = fmaf(dec_hi(qw), kF, cF);
    }
}

extern "C" void kernel_launch(void* const* d_in, const int* in_sizes, int n_in,
                              void* d_out, int out_size) {
    const float* x = (const float*)d_in[0];   // (B, G) float32
    const int*   I = (const int*)d_in[1];     // (C, G, S, L) int32

    transpose_I_kernel<<<(NC * NG * NS) / 256, 256>>>(I);

    dim3 gridA(NG / 256, NBG, NC);            // (8, 8, 16) = 1024 blocks
    for (int t = 0; t < NSTEPS; t++) {
        clause_kernel<<<gridA, 256>>>(x, t);
        combine_kernel<<<NPK / 256, 256>>>(x, t);
    }
    final_kernel<<<NPK / 256, 256>>>((float*)d_out);
}